// round 1
// baseline (speedup 1.0000x reference)
#include <cuda_runtime.h>

// ---------------------------------------------------------------------------
// Problem constants
//   B=2, N=1024, E=512, H=8, d=64, KVC=1536, 3N=3072
// ---------------------------------------------------------------------------

// Scratch (static __device__ arrays; no allocation anywhere)
__device__ float g_QC  [2*1024*1536];
__device__ float g_KC  [2*1024*1536];
__device__ float g_VC  [2*1024*1536];
__device__ float g_ATTC[2*1536*1536];
__device__ float g_CTXC[2*1536*1024];
__device__ float g_KVS [2*3072*512];
__device__ float g_KM  [2*3072*512];
__device__ float g_VM  [2*3072*512];
__device__ float g_QB  [2*1024*512];
__device__ float g_ATT [2*8*1024*3072];     // 201 MB, reused per stream
__device__ float g_CTXP[6*2*1024*512];      // split-K partials
__device__ float g_CTXB[2*1024*512];
__device__ float g_PART[16*256*2];
__device__ float g_SCALE[16];

// ---------------------------------------------------------------------------
// Generic tiled GEMM:
//   C[m,n] = sum_k Aelem(m,k) * Belem(n,k)
//   TA==0: Aelem(m,k)=A[m*lda+k]   TA==1: Aelem(m,k)=A[k*lda+m]
//   TB==0: Belem(n,k)=B[n*ldb+k]   TB==1: Belem(n,k)=B[k*ldb+n]
// z-batching: z -> (zk, zo, zi) with r=z%bhTotal, zo=r/innerB, zi=r%innerB,
// zk=z/bhTotal (split-K slice); pointer offsets applied per index.
// Requires: blockDim.x == (BM/TM)*(BN/TN) == 256, BM*BK/4==256, BN*BK/4==256,
// K multiple of BK, TM,TN multiples of 4.
// ---------------------------------------------------------------------------
template<int TA,int TB,int BM,int BN,int BK,int TM,int TN>
__global__ __launch_bounds__(256)
void gemm_k(const float* __restrict__ A, const float* __restrict__ B,
            float* __restrict__ C,
            int M, int Nd, int K, int lda, int ldb, int ldc,
            long sAo, long sAi, long sBo, long sBi, long sCo, long sCi,
            int innerB, int bhTotal, long kOffA, long kOffB, long kOffC)
{
    int z  = blockIdx.z;
    int zk = z / bhTotal;
    int r  = z % bhTotal;
    int zo = r / innerB;
    int zi = r % innerB;
    A += (long)zo*sAo + (long)zi*sAi + (long)zk*kOffA;
    B += (long)zo*sBo + (long)zi*sBi + (long)zk*kOffB;
    C += (long)zo*sCo + (long)zi*sCi + (long)zk*kOffC;

    __shared__ float As[BK][BM];
    __shared__ float Bs[BK][BN];

    const int tid = threadIdx.x;
    const int tm  = tid / (BN/TN);
    const int tn  = tid % (BN/TN);
    const int m0  = blockIdx.y * BM;
    const int n0  = blockIdx.x * BN;

    float acc[TM][TN];
#pragma unroll
    for (int i=0;i<TM;i++)
#pragma unroll
        for (int j=0;j<TN;j++) acc[i][j] = 0.f;

    for (int k0 = 0; k0 < K; k0 += BK) {
        // ---- load A tile: As[k][m] = Aelem(m0+m, k0+k) ----
        if constexpr (TA == 0) {
            constexpr int TPR = BK/4;
            int m  = tid / TPR;
            int kk = (tid % TPR) * 4;
            bool inM = (m0+m) < M;
            const float* src = A + (long)(m0+m)*lda + (k0+kk);
#pragma unroll
            for (int u=0;u<4;u++)
                As[kk+u][m] = inM ? src[u] : 0.f;
        } else {
            constexpr int TPR = BM/4;
            int kk = tid / TPR;
            int m  = (tid % TPR) * 4;
            const float* src = A + (long)(k0+kk)*lda + (m0+m);
#pragma unroll
            for (int u=0;u<4;u++)
                As[kk][m+u] = ((m0+m+u) < M) ? src[u] : 0.f;
        }
        // ---- load B tile: Bs[k][n] = Belem(n0+n, k0+k) ----
        if constexpr (TB == 0) {
            constexpr int TPR = BK/4;
            int n  = tid / TPR;
            int kk = (tid % TPR) * 4;
            bool inN = (n0+n) < Nd;
            const float* src = B + (long)(n0+n)*ldb + (k0+kk);
#pragma unroll
            for (int u=0;u<4;u++)
                Bs[kk+u][n] = inN ? src[u] : 0.f;
        } else {
            constexpr int TPR = BN/4;
            int kk = tid / TPR;
            int n  = (tid % TPR) * 4;
            const float* src = B + (long)(k0+kk)*ldb + (n0+n);
#pragma unroll
            for (int u=0;u<4;u++)
                Bs[kk][n+u] = ((n0+n+u) < Nd) ? src[u] : 0.f;
        }
        __syncthreads();

#pragma unroll
        for (int k=0;k<BK;k++) {
            float a[TM], b[TN];
#pragma unroll
            for (int i=0;i<TM;i+=4)
                *(float4*)&a[i] = *(const float4*)&As[k][tm*TM + i];
#pragma unroll
            for (int j=0;j<TN;j+=4)
                *(float4*)&b[j] = *(const float4*)&Bs[k][tn*TN + j];
#pragma unroll
            for (int i=0;i<TM;i++)
#pragma unroll
                for (int j=0;j<TN;j++)
                    acc[i][j] += a[i]*b[j];
        }
        __syncthreads();
    }

#pragma unroll
    for (int i=0;i<TM;i++) {
        int mg = m0 + tm*TM + i;
        if (mg >= M) continue;
        float* crow = C + (long)mg*ldc;
#pragma unroll
        for (int j=0;j<TN;j++) {
            int ng = n0 + tn*TN + j;
            if (ng < Nd) crow[ng] = acc[i][j];
        }
    }
}

// ---------------------------------------------------------------------------
// Deterministic two-pass global (sum, sumsq) per z-slice
// ---------------------------------------------------------------------------
__global__ __launch_bounds__(256)
void stats_partial(const float* __restrict__ x, long perZ,
                   float* __restrict__ part, int nblk)
{
    long z = blockIdx.y;
    const float* p = x + z*perZ;
    float s = 0.f, ss = 0.f;
    long start  = (long)blockIdx.x*256 + threadIdx.x;
    long stride = (long)nblk*256;
    for (long i = start; i < perZ; i += stride) {
        float v = p[i];
        s += v;
        ss = fmaf(v, v, ss);
    }
    __shared__ float a[256], b2[256];
    a[threadIdx.x] = s; b2[threadIdx.x] = ss;
    __syncthreads();
    for (int o=128;o>0;o>>=1) {
        if (threadIdx.x < o) { a[threadIdx.x]+=a[threadIdx.x+o]; b2[threadIdx.x]+=b2[threadIdx.x+o]; }
        __syncthreads();
    }
    if (threadIdx.x == 0) {
        long idx = (z*nblk + blockIdx.x)*2;
        part[idx] = a[0]; part[idx+1] = b2[0];
    }
}

__global__ __launch_bounds__(256)
void stats_final(const float* __restrict__ part, int nblk, long perZ,
                 float* __restrict__ scale)
{
    int z = blockIdx.x;
    float s = 0.f, ss = 0.f;
    for (int i = threadIdx.x; i < nblk; i += 256) {
        s  += part[((long)z*nblk + i)*2];
        ss += part[((long)z*nblk + i)*2 + 1];
    }
    __shared__ float a[256], b2[256];
    a[threadIdx.x] = s; b2[threadIdx.x] = ss;
    __syncthreads();
    for (int o=128;o>0;o>>=1) {
        if (threadIdx.x < o) { a[threadIdx.x]+=a[threadIdx.x+o]; b2[threadIdx.x]+=b2[threadIdx.x+o]; }
        __syncthreads();
    }
    if (threadIdx.x == 0) {
        float mu  = a[0] / (float)perZ;
        float var = b2[0] / (float)perZ - mu*mu;
        scale[z]  = rsqrtf(fmaxf(var, 0.f) + 1e-5f);
    }
}

// ---------------------------------------------------------------------------
// Row softmax of scale[row/rowsPerScale] * x[row,:]  (instance-norm mean
// cancels inside softmax — only the rsqrt(var+eps) scale matters).
// One block (256 threads) per row; row kept in registers (PER = L/256).
// ---------------------------------------------------------------------------
template<int PER>
__global__ __launch_bounds__(256)
void softmax_rows(float* __restrict__ x, int L,
                  const float* __restrict__ scale, int rowsPerScale)
{
    long row = blockIdx.x;
    float s  = scale[row / rowsPerScale];
    float* p = x + row*(long)L;

    float v[PER];
    float mx = -1e30f;
#pragma unroll
    for (int i=0;i<PER;i++) {
        v[i] = p[threadIdx.x + i*256] * s;
        mx = fmaxf(mx, v[i]);
    }
    __shared__ float sh[8];
    for (int o=16;o>0;o>>=1) mx = fmaxf(mx, __shfl_xor_sync(0xffffffffu, mx, o));
    if ((threadIdx.x & 31) == 0) sh[threadIdx.x >> 5] = mx;
    __syncthreads();
    mx = sh[0];
#pragma unroll
    for (int i=1;i<8;i++) mx = fmaxf(mx, sh[i]);

    float sum = 0.f;
#pragma unroll
    for (int i=0;i<PER;i++) { v[i] = __expf(v[i]-mx); sum += v[i]; }
    __shared__ float sh2[8];
    for (int o=16;o>0;o>>=1) sum += __shfl_xor_sync(0xffffffffu, sum, o);
    if ((threadIdx.x & 31) == 0) sh2[threadIdx.x >> 5] = sum;
    __syncthreads();
    sum = 0.f;
#pragma unroll
    for (int i=0;i<8;i++) sum += sh2[i];

    float inv = 1.0f / sum;
#pragma unroll
    for (int i=0;i<PER;i++) p[threadIdx.x + i*256] = v[i]*inv;
}

// ---------------------------------------------------------------------------
// KV_S build: kvs[b][j*1024+n][e] = ctx_c[b][j*512+e][n]  (tiled transpose)
// grid (32, 16, 6) block (32, 8)
// ---------------------------------------------------------------------------
__global__ void kvs_transpose(const float* __restrict__ ctxc, float* __restrict__ kvs)
{
    int z = blockIdx.z;
    int b = z / 3, j = z % 3;
    const float* src = ctxc + (long)b*1536*1024 + (long)j*512*1024;   // [512 e][1024 n]
    float*       dst = kvs  + (long)b*3072*512  + (long)j*1024*512;   // [1024 n][512 e]

    __shared__ float t[32][33];
    int n0 = blockIdx.x*32, e0 = blockIdx.y*32;
    int tx = threadIdx.x, ty = threadIdx.y;
#pragma unroll
    for (int i=0;i<32;i+=8)
        t[ty+i][tx] = src[(long)(e0+ty+i)*1024 + (n0+tx)];
    __syncthreads();
#pragma unroll
    for (int i=0;i<32;i+=8)
        dst[(long)(n0+ty+i)*512 + (e0+tx)] = t[tx][ty+i];
}

__global__ __launch_bounds__(256)
void sum_slices(const float* __restrict__ part, float* __restrict__ out, long n, int slices)
{
    long i = (long)blockIdx.x*256 + threadIdx.x;
    if (i < n) {
        float s = 0.f;
        for (int k=0;k<slices;k++) s += part[(long)k*n + i];
        out[i] = s;
    }
}

// ---------------------------------------------------------------------------
// Host orchestration (graph-capturable: kernel launches only)
// ---------------------------------------------------------------------------
extern "C" void kernel_launch(void* const* d_in, const int* in_sizes, int n_in,
                              void* d_out, int out_size)
{
    const float* emb[3] = {(const float*)d_in[0], (const float*)d_in[1], (const float*)d_in[2]};
    const float* embC   = (const float*)d_in[3];
    const float* Wq[3]  = {(const float*)d_in[4], (const float*)d_in[5], (const float*)d_in[6]};
    const float* Wk     = (const float*)d_in[7];
    const float* Wv     = (const float*)d_in[8];
    const float* WqC    = (const float*)d_in[9];
    const float* WkC    = (const float*)d_in[10];
    const float* WvC    = (const float*)d_in[11];
    const float* Wo[3]  = {(const float*)d_in[12], (const float*)d_in[13], (const float*)d_in[14]};
    float* out = (float*)d_out;

    float *QC,*KC,*VC,*ATTC,*CTXC,*KVS,*KM,*VM,*QB,*ATT,*CTXP,*CTXB,*PART,*SCALE;
    cudaGetSymbolAddress((void**)&QC,   g_QC);
    cudaGetSymbolAddress((void**)&KC,   g_KC);
    cudaGetSymbolAddress((void**)&VC,   g_VC);
    cudaGetSymbolAddress((void**)&ATTC, g_ATTC);
    cudaGetSymbolAddress((void**)&CTXC, g_CTXC);
    cudaGetSymbolAddress((void**)&KVS,  g_KVS);
    cudaGetSymbolAddress((void**)&KM,   g_KM);
    cudaGetSymbolAddress((void**)&VM,   g_VM);
    cudaGetSymbolAddress((void**)&QB,   g_QB);
    cudaGetSymbolAddress((void**)&ATT,  g_ATT);
    cudaGetSymbolAddress((void**)&CTXP, g_CTXP);
    cudaGetSymbolAddress((void**)&CTXB, g_CTXB);
    cudaGetSymbolAddress((void**)&PART, g_PART);
    cudaGetSymbolAddress((void**)&SCALE,g_SCALE);

    // ---- 1) Channel projections: [2048,1536] = embC(flat) @ W^T ----
    {
        dim3 g(1536/128, 2048/128, 1);
        gemm_k<0,0,128,128,8,8,8><<<g,256>>>(embC, WqC, QC, 2048,1536,1536, 1536,1536,1536,
                                             0,0,0,0,0,0, 1,1, 0,0,0);
        gemm_k<0,0,128,128,8,8,8><<<g,256>>>(embC, WkC, KC, 2048,1536,1536, 1536,1536,1536,
                                             0,0,0,0,0,0, 1,1, 0,0,0);
        gemm_k<0,0,128,128,8,8,8><<<g,256>>>(embC, WvC, VC, 2048,1536,1536, 1536,1536,1536,
                                             0,0,0,0,0,0, 1,1, 0,0,0);
    }

    // ---- 2) attn_c[b] = QC[b]^T @ KC[b]  (TN), [1536,1536], K=1024 ----
    gemm_k<1,1,128,128,8,8,8><<<dim3(12,12,2),256>>>(QC, KC, ATTC, 1536,1536,1024, 1536,1536,1536,
                                                     1572864,0, 1572864,0, 2359296,0, 1,2, 0,0,0);

    // ---- 3) channel instance-norm scale + row softmax ----
    stats_partial<<<dim3(256,2),256>>>(ATTC, 2359296L, PART, 256);
    stats_final  <<<2,256>>>(PART, 256, 2359296L, SCALE);
    softmax_rows<6><<<2*1536,256>>>(ATTC, 1536, SCALE, 1536);

    // ---- 4) ctx_c[b] = sim[b] @ VC[b]^T : [1536,1024], K=1536 ----
    gemm_k<0,0,128,128,8,8,8><<<dim3(8,12,2),256>>>(ATTC, VC, CTXC, 1536,1024,1536, 1536,1536,1024,
                                                    2359296,0, 1572864,0, 1572864,0, 1,2, 0,0,0);

    // ---- 5) KV_S = reshuffle(ctx_c) ----
    kvs_transpose<<<dim3(32,16,6),dim3(32,8)>>>(CTXC, KVS);

    // ---- 6) K/V projections: [6144,512] = KVS @ W^T ----
    gemm_k<0,0,128,128,8,8,8><<<dim3(4,48,1),256>>>(KVS, Wk, KM, 6144,512,512, 512,512,512,
                                                    0,0,0,0,0,0, 1,1, 0,0,0);
    gemm_k<0,0,128,128,8,8,8><<<dim3(4,48,1),256>>>(KVS, Wv, VM, 6144,512,512, 512,512,512,
                                                    0,0,0,0,0,0, 1,1, 0,0,0);

    // ---- 7) three spatial streams ----
    for (int s = 0; s < 3; s++) {
        // Q projection [2048,512]
        gemm_k<0,0,128,128,8,8,8><<<dim3(4,16,1),256>>>(emb[s], Wq[s], QB, 2048,512,512, 512,512,512,
                                                        0,0,0,0,0,0, 1,1, 0,0,0);
        // attn[b,h] = Q_h @ K_h^T : [1024,3072], K=64, z=(b,h)
        gemm_k<0,0,128,128,8,8,8><<<dim3(24,8,16),256>>>(QB, KM, ATT, 1024,3072,64, 512,512,3072,
                                                         524288,64, 1572864,64, 25165824,3145728,
                                                         8,16, 0,0,0);
        // per-(b,h) instance-norm scale + row softmax
        stats_partial<<<dim3(256,16),256>>>(ATT, 3145728L, PART, 256);
        stats_final  <<<16,256>>>(PART, 256, 3145728L, SCALE);
        softmax_rows<12><<<16384,256>>>(ATT, 3072, SCALE, 1024);
        // ctx = sim @ V_h : [1024,64] per (b,h), K=3072 -> split-K=6 (K slices of 512)
        gemm_k<0,1,64,64,16,4,4><<<dim3(1,16,96),256>>>(ATT, VM, CTXP, 1024,64,512, 3072,512,512,
                                                        25165824,3145728, 1572864,64, 524288,64,
                                                        8,16, 512, 262144, 1048576);
        sum_slices<<<(1048576+255)/256,256>>>(CTXP, CTXB, 1048576L, 6);
        // O = ctx @ Wo^T -> d_out slice
        gemm_k<0,0,128,128,8,8,8><<<dim3(4,16,1),256>>>(CTXB, Wo[s], out + (long)s*1048576,
                                                        2048,512,512, 512,512,512,
                                                        0,0,0,0,0,0, 1,1, 0,0,0);
    }
}

// round 3
// speedup vs baseline: 3.4612x; 3.4612x over previous
#include <cuda_runtime.h>
#include <cstdint>

// ===========================================================================
// Problem: B=2, N=1024, E=512, H=8, d=64, KVC=1536, 3N=3072
// All GEMMs via mma.sync.m16n8k8 tf32 (target-portable tensor core path;
// tcgen05 requires sm_103a-specific target which this harness doesn't use).
// ===========================================================================

// ------------------------- scratch (__device__ globals) -------------------
__device__ float g_QCt [2*1536*1024];
__device__ float g_KCt [2*1536*1024];
__device__ float g_VC  [2*1024*1536];
__device__ float g_ATTC[2*1536*1536];
__device__ float g_CTXC[2*1536*1024];
__device__ float g_KVS [2*3072*512];
__device__ float g_KM  [2*3072*512];
__device__ float g_VMt [2*512*3072];
__device__ float g_QB  [2*1024*512];
__device__ float g_ATT [16*1024*3072];   // 201 MB, reused per stream
__device__ float g_CTXB[2*1024*512];
__device__ float g_PART[16*256*2];
__device__ float g_SCALE[16];

// ------------------------- helpers ----------------------------------------
__device__ __forceinline__ uint32_t tf32rn(float x) {
    uint32_t r;
    asm("cvt.rna.tf32.f32 %0, %1;" : "=r"(r) : "f"(x));
    return r;
}

__device__ __forceinline__ void mma1688(float* c, const uint32_t* a, const uint32_t* b) {
    asm volatile(
        "mma.sync.aligned.m16n8k8.row.col.f32.tf32.tf32.f32 "
        "{%0,%1,%2,%3}, {%4,%5,%6,%7}, {%8,%9}, {%0,%1,%2,%3};"
        : "+f"(c[0]), "+f"(c[1]), "+f"(c[2]), "+f"(c[3])
        : "r"(a[0]), "r"(a[1]), "r"(a[2]), "r"(a[3]), "r"(b[0]), "r"(b[1]));
}

// ===========================================================================
// Tensor-core GEMM:  C[m,n] = sum_k A[m*lda+k] * B[n*ldb+k]   (K-major both)
//   BM=128 fixed, BN in {64,128}, BK=32. M%128==0, N%BN==0, K%32==0.
//   z-batch: zo=z/innerB, zi=z%innerB with per-operand strides.
//   STATS: per-block (sum, sumsq) partials -> part[(z*nblk+blk)*2 ..]
// ===========================================================================
template<int BN, bool STATS>
__global__ __launch_bounds__(256)
void mma_gemm(const float* __restrict__ A, const float* __restrict__ B, float* __restrict__ C,
              int K, int lda, int ldb, int ldc,
              long sAo, long sAi, long sBo, long sBi, long sCo, long sCi,
              int innerB, float* __restrict__ part)
{
    constexpr int BM  = 128, BK = 32, PAD = 36;
    constexpr int WGN = (BN == 128) ? 4 : 2;      // warps along n
    constexpr int WM  = (BN == 128) ? 64 : 32;    // warp tile m
    constexpr int WN  = 32;                       // warp tile n
    constexpr int MT  = WM / 16;                  // mma tiles per warp (m)
    constexpr int NT  = WN / 8;                   // mma tiles per warp (n)
    constexpr int PBN = BN / 32;                  // B float4 loads per thread

    __shared__ uint32_t As[BM * PAD];
    __shared__ uint32_t Bs[BN * PAD];

    const int z  = blockIdx.z;
    const int zo = z / innerB, zi = z % innerB;
    A += (long)zo * sAo + (long)zi * sAi;
    B += (long)zo * sBo + (long)zi * sBi;
    C += (long)zo * sCo + (long)zi * sCi;

    const int m0  = blockIdx.y * BM;
    const int n0  = blockIdx.x * BN;
    const int tid = threadIdx.x;
    const int wid = tid >> 5, lane = tid & 31;
    const int gid = lane >> 2, tig = lane & 3;
    const int wm  = wid / WGN, wn = wid % WGN;

    // global load mapping: 32 rows x 8 float4 per pass
    const int lr = tid >> 3;
    const int lc = (tid & 7) * 4;
    const float* Aptr = A + (long)(m0 + lr) * lda + lc;
    const float* Bptr = B + (long)(n0 + lr) * ldb + lc;

    float4 pa[4], pb[PBN];
    const int T = K / BK;

    // prefetch tile 0
#pragma unroll
    for (int i = 0; i < 4; i++)   pa[i] = *(const float4*)(Aptr + (long)(32*i) * lda);
#pragma unroll
    for (int i = 0; i < PBN; i++) pb[i] = *(const float4*)(Bptr + (long)(32*i) * ldb);

    float cacc[MT][NT][4];
#pragma unroll
    for (int mt = 0; mt < MT; mt++)
#pragma unroll
        for (int nt = 0; nt < NT; nt++)
#pragma unroll
            for (int r = 0; r < 4; r++) cacc[mt][nt][r] = 0.f;

    for (int kt = 0; kt < T; kt++) {
        if (kt > 0) __syncthreads();   // previous compute done before overwrite
        // store (with tf32 round-to-nearest) into smem
#pragma unroll
        for (int i = 0; i < 4; i++) {
            uint32_t* d = &As[(lr + 32*i) * PAD + lc];
            d[0] = tf32rn(pa[i].x); d[1] = tf32rn(pa[i].y);
            d[2] = tf32rn(pa[i].z); d[3] = tf32rn(pa[i].w);
        }
#pragma unroll
        for (int i = 0; i < PBN; i++) {
            uint32_t* d = &Bs[(lr + 32*i) * PAD + lc];
            d[0] = tf32rn(pb[i].x); d[1] = tf32rn(pb[i].y);
            d[2] = tf32rn(pb[i].z); d[3] = tf32rn(pb[i].w);
        }
        __syncthreads();
        // prefetch next tile
        if (kt + 1 < T) {
            const float* An = Aptr + (kt + 1) * BK;
            const float* Bn = Bptr + (kt + 1) * BK;
#pragma unroll
            for (int i = 0; i < 4; i++)   pa[i] = *(const float4*)(An + (long)(32*i) * lda);
#pragma unroll
            for (int i = 0; i < PBN; i++) pb[i] = *(const float4*)(Bn + (long)(32*i) * ldb);
        }
        // compute: 4 k-steps of 8
#pragma unroll
        for (int ks = 0; ks < 4; ks++) {
            uint32_t af[MT][4], bf[NT][2];
#pragma unroll
            for (int mt = 0; mt < MT; mt++) {
                const uint32_t* p = &As[(wm*WM + mt*16 + gid) * PAD + ks*8 + tig];
                af[mt][0] = p[0];
                af[mt][1] = p[8*PAD];
                af[mt][2] = p[4];
                af[mt][3] = p[8*PAD + 4];
            }
#pragma unroll
            for (int nt = 0; nt < NT; nt++) {
                const uint32_t* p = &Bs[(wn*WN + nt*8 + gid) * PAD + ks*8 + tig];
                bf[nt][0] = p[0];
                bf[nt][1] = p[4];
            }
#pragma unroll
            for (int mt = 0; mt < MT; mt++)
#pragma unroll
                for (int nt = 0; nt < NT; nt++)
                    mma1688(cacc[mt][nt], af[mt], bf[nt]);
        }
    }

    if (STATS) {
        float s = 0.f, ss = 0.f;
#pragma unroll
        for (int mt = 0; mt < MT; mt++)
#pragma unroll
            for (int nt = 0; nt < NT; nt++)
#pragma unroll
                for (int r = 0; r < 4; r++) {
                    float v = cacc[mt][nt][r];
                    s += v; ss = fmaf(v, v, ss);
                }
        __shared__ float reds[256], redq[256];
        reds[tid] = s; redq[tid] = ss;
        __syncthreads();
        for (int o = 128; o > 0; o >>= 1) {
            if (tid < o) { reds[tid] += reds[tid+o]; redq[tid] += redq[tid+o]; }
            __syncthreads();
        }
        if (tid == 0) {
            int nblk  = gridDim.x * gridDim.y;
            int blkId = blockIdx.y * gridDim.x + blockIdx.x;
            long idx  = ((long)z * nblk + blkId) * 2;
            part[idx] = reds[0]; part[idx+1] = redq[0];
        }
    }

    // epilogue: direct float2 stores (c0,c1 rows gid; c2,c3 rows gid+8)
#pragma unroll
    for (int mt = 0; mt < MT; mt++) {
        const int row = m0 + wm*WM + mt*16 + gid;
#pragma unroll
        for (int nt = 0; nt < NT; nt++) {
            const int col = n0 + wn*WN + nt*8 + tig*2;
            float2 v0 = make_float2(cacc[mt][nt][0], cacc[mt][nt][1]);
            float2 v1 = make_float2(cacc[mt][nt][2], cacc[mt][nt][3]);
            *(float2*)&C[(long)row * ldc + col]       = v0;
            *(float2*)&C[(long)(row + 8) * ldc + col] = v1;
        }
    }
}

// ---------------------------------------------------------------------------
// stats_final: reduce per-block partials -> scale = rsqrt(var + eps)
// ---------------------------------------------------------------------------
__global__ __launch_bounds__(256)
void stats_final(const float* __restrict__ part, int nblk, long perZ,
                 float* __restrict__ scale)
{
    int z = blockIdx.x;
    float s = 0.f, ss = 0.f;
    for (int i = threadIdx.x; i < nblk; i += 256) {
        s  += part[((long)z*nblk + i)*2];
        ss += part[((long)z*nblk + i)*2 + 1];
    }
    __shared__ float a[256], b2[256];
    a[threadIdx.x] = s; b2[threadIdx.x] = ss;
    __syncthreads();
    for (int o = 128; o > 0; o >>= 1) {
        if (threadIdx.x < o) { a[threadIdx.x] += a[threadIdx.x+o]; b2[threadIdx.x] += b2[threadIdx.x+o]; }
        __syncthreads();
    }
    if (threadIdx.x == 0) {
        float mu  = a[0] / (float)perZ;
        float var = b2[0] / (float)perZ - mu*mu;
        scale[z]  = rsqrtf(fmaxf(var, 0.f) + 1e-5f);
    }
}

// ---------------------------------------------------------------------------
// Row softmax of scale * x  (instance-norm mean cancels inside softmax)
// ---------------------------------------------------------------------------
template<int PER>
__global__ __launch_bounds__(256)
void softmax_rows(float* __restrict__ x, int L,
                  const float* __restrict__ scale, int rowsPerScale)
{
    long row = blockIdx.x;
    float s  = scale[row / rowsPerScale];
    float* p = x + row * (long)L;

    float v[PER];
    float mx = -1e30f;
#pragma unroll
    for (int i = 0; i < PER; i++) {
        v[i] = p[threadIdx.x + i*256] * s;
        mx = fmaxf(mx, v[i]);
    }
    __shared__ float sh[8];
    for (int o = 16; o > 0; o >>= 1) mx = fmaxf(mx, __shfl_xor_sync(0xffffffffu, mx, o));
    if ((threadIdx.x & 31) == 0) sh[threadIdx.x >> 5] = mx;
    __syncthreads();
    mx = sh[0];
#pragma unroll
    for (int i = 1; i < 8; i++) mx = fmaxf(mx, sh[i]);

    float sum = 0.f;
#pragma unroll
    for (int i = 0; i < PER; i++) { v[i] = __expf(v[i] - mx); sum += v[i]; }
    __shared__ float sh2[8];
    for (int o = 16; o > 0; o >>= 1) sum += __shfl_xor_sync(0xffffffffu, sum, o);
    if ((threadIdx.x & 31) == 0) sh2[threadIdx.x >> 5] = sum;
    __syncthreads();
    sum = 0.f;
#pragma unroll
    for (int i = 0; i < 8; i++) sum += sh2[i];

    float inv = 1.0f / sum;
#pragma unroll
    for (int i = 0; i < PER; i++) p[threadIdx.x + i*256] = v[i] * inv;
}

// ---------------------------------------------------------------------------
// KV_S build: kvs[b][j*1024+n][e] = ctx_c[b][j*512+e][n]  (tiled transpose)
// ---------------------------------------------------------------------------
__global__ void kvs_transpose(const float* __restrict__ ctxc, float* __restrict__ kvs)
{
    int z = blockIdx.z;
    int b = z / 3, j = z % 3;
    const float* src = ctxc + (long)b*1536*1024 + (long)j*512*1024;
    float*       dst = kvs  + (long)b*3072*512  + (long)j*1024*512;

    __shared__ float t[32][33];
    int n0 = blockIdx.x*32, e0 = blockIdx.y*32;
    int tx = threadIdx.x, ty = threadIdx.y;
#pragma unroll
    for (int i = 0; i < 32; i += 8)
        t[ty+i][tx] = src[(long)(e0+ty+i)*1024 + (n0+tx)];
    __syncthreads();
#pragma unroll
    for (int i = 0; i < 32; i += 8)
        dst[(long)(n0+ty+i)*512 + (e0+tx)] = t[tx][ty+i];
}

// ---------------------------------------------------------------------------
// Host orchestration (graph-capturable: kernel launches only)
// ---------------------------------------------------------------------------
extern "C" void kernel_launch(void* const* d_in, const int* in_sizes, int n_in,
                              void* d_out, int out_size)
{
    const float* emb[3] = {(const float*)d_in[0], (const float*)d_in[1], (const float*)d_in[2]};
    const float* embC   = (const float*)d_in[3];
    const float* Wq[3]  = {(const float*)d_in[4], (const float*)d_in[5], (const float*)d_in[6]};
    const float* Wk     = (const float*)d_in[7];
    const float* Wv     = (const float*)d_in[8];
    const float* WqC    = (const float*)d_in[9];
    const float* WkC    = (const float*)d_in[10];
    const float* WvC    = (const float*)d_in[11];
    const float* Wo[3]  = {(const float*)d_in[12], (const float*)d_in[13], (const float*)d_in[14]};
    float* out = (float*)d_out;

    float *QCt,*KCt,*VC,*ATTC,*CTXC,*KVS,*KM,*VMt,*QB,*ATT,*CTXB,*PART,*SCALE;
    cudaGetSymbolAddress((void**)&QCt,  g_QCt);
    cudaGetSymbolAddress((void**)&KCt,  g_KCt);
    cudaGetSymbolAddress((void**)&VC,   g_VC);
    cudaGetSymbolAddress((void**)&ATTC, g_ATTC);
    cudaGetSymbolAddress((void**)&CTXC, g_CTXC);
    cudaGetSymbolAddress((void**)&KVS,  g_KVS);
    cudaGetSymbolAddress((void**)&KM,   g_KM);
    cudaGetSymbolAddress((void**)&VMt,  g_VMt);
    cudaGetSymbolAddress((void**)&QB,   g_QB);
    cudaGetSymbolAddress((void**)&ATT,  g_ATT);
    cudaGetSymbolAddress((void**)&CTXB, g_CTXB);
    cudaGetSymbolAddress((void**)&PART, g_PART);
    cudaGetSymbolAddress((void**)&SCALE,g_SCALE);

    // ---- 1) QCt[b] = WqC @ embC[b]^T, KCt[b] = WkC @ embC[b]^T  [1536,1024]
    mma_gemm<128,false><<<dim3(8,12,2),256>>>(WqC, embC, QCt, 1536, 1536,1536,1024,
        0,0, 1572864,0, 1572864,0, 1, nullptr);
    mma_gemm<128,false><<<dim3(8,12,2),256>>>(WkC, embC, KCt, 1536, 1536,1536,1024,
        0,0, 1572864,0, 1572864,0, 1, nullptr);
    // ---- VC = embC @ WvC^T  [2048,1536]
    mma_gemm<128,false><<<dim3(12,16,1),256>>>(embC, WvC, VC, 1536, 1536,1536,1536,
        0,0, 0,0, 0,0, 1, nullptr);

    // ---- 2) attn_c[b][c,d] = sum_n QCt[c,n]*KCt[d,n]  [1536,1536], K=1024
    mma_gemm<128,true><<<dim3(12,12,2),256>>>(QCt, KCt, ATTC, 1024, 1024,1024,1536,
        1572864,0, 1572864,0, 2359296,0, 1, PART);
    stats_final<<<2,256>>>(PART, 144, 2359296L, SCALE);
    softmax_rows<6><<<2*1536,256>>>(ATTC, 1536, SCALE, 1536);

    // ---- 3) ctx_c[b] = sim[b] @ VC[b]   [1536,1024], K=1536
    mma_gemm<128,false><<<dim3(8,12,2),256>>>(ATTC, VC, CTXC, 1536, 1536,1536,1024,
        2359296,0, 1572864,0, 1572864,0, 1, nullptr);

    // ---- 4) KV_S reshuffle
    kvs_transpose<<<dim3(32,16,6),dim3(32,8)>>>(CTXC, KVS);

    // ---- 5) KM = KVS @ Wk^T [6144,512];  VMt[b] = Wv @ KVS[b]^T [512,3072]
    mma_gemm<128,false><<<dim3(4,48,1),256>>>(KVS, Wk, KM, 512, 512,512,512,
        0,0, 0,0, 0,0, 1, nullptr);
    mma_gemm<128,false><<<dim3(24,4,2),256>>>(Wv, KVS, VMt, 512, 512,512,3072,
        0,0, 1572864,0, 1572864,0, 1, nullptr);

    // ---- 6) three spatial streams ----
    for (int s = 0; s < 3; s++) {
        // QB = emb[s] @ Wq^T  [2048,512]
        mma_gemm<128,false><<<dim3(4,16,1),256>>>(emb[s], Wq[s], QB, 512, 512,512,512,
            0,0, 0,0, 0,0, 1, nullptr);
        // ATT[z=(b,h)] = Q_h @ K_h^T  [1024,3072], K=64
        mma_gemm<128,true><<<dim3(24,8,16),256>>>(QB, KM, ATT, 64, 512,512,3072,
            524288,64, 1572864,64, 25165824,3145728, 8, PART);
        stats_final<<<16,256>>>(PART, 192, 3145728L, SCALE);
        softmax_rows<12><<<16384,256>>>(ATT, 3072, SCALE, 1024);
        // ctx[z=(b,h)] = sim @ V_h  [1024,64], K=3072
        mma_gemm<64,false><<<dim3(1,8,16),256>>>(ATT, VMt, CTXB, 3072, 3072,3072,512,
            25165824,3145728, 1572864,196608, 524288,64, 8, nullptr);
        // O = ctx @ Wo^T -> d_out slice  [2048,512]
        mma_gemm<128,false><<<dim3(4,16,1),256>>>(CTXB, Wo[s], out + (long)s*1048576,
            512, 512,512,512, 0,0, 0,0, 0,0, 1, nullptr);
    }
}